// round 2
// baseline (speedup 1.0000x reference)
#include <cuda_runtime.h>

#define H     8192
#define NN    81
#define NE    1620
#define IND   10
#define ACT   729

// ---- scratch (static device allocation: allowed) ----
__device__ float g_z[NN * H];       // post-relu GCN output [81, 8192]
__device__ float g_stats[2 * NN];   // mu[81], rstd[81]
__device__ float g_g[H];            // pooled LN vector
__device__ float g_y[H];            // g @ W1 accumulator (pre-bias, pre-relu)
__device__ float g_logits[ACT];     // y_act @ W2 accumulator (pre-bias)

// ---------------------------------------------------------------------------
// K1: GCN conv + relu -> g_z.  Each block owns 32 hidden columns; builds the
// dense normalized adjacency M (81x81, incl. self-loops) redundantly in smem.
// ---------------------------------------------------------------------------
__global__ void k1_gcn(const float* __restrict__ x,
                       const int* __restrict__ ei,      // int32 edge_index [2,1620]
                       const float* __restrict__ Wg,
                       const float* __restrict__ bg) {
    __shared__ float x_s[NN * IND];      // 810
    __shared__ float dinv[NN];           // deg -> rsqrt(deg)
    __shared__ float M[NN * NN];         // 6561
    __shared__ float wg_s[IND * 32];     // W_gcn slice
    __shared__ float h_s[NN * 32];       // x@W slice
    const int tid  = threadIdx.x;
    const int col0 = blockIdx.x * 32;

    for (int i = tid; i < NN * IND; i += 256) x_s[i] = x[i];
    if (tid < NN) dinv[tid] = 1.0f;                       // self-loop
    for (int i = tid; i < NN * NN; i += 256) M[i] = 0.f;
    for (int i = tid; i < IND * 32; i += 256)
        wg_s[i] = Wg[(i >> 5) * H + col0 + (i & 31)];
    __syncthreads();

    for (int e = tid; e < NE; e += 256)
        atomicAdd(&dinv[ei[NE + e]], 1.f);                // in-degree at dst
    __syncthreads();
    if (tid < NN) dinv[tid] = rsqrtf(dinv[tid]);
    __syncthreads();

    for (int e = tid; e < NE; e += 256) {
        int s = ei[e], d = ei[NE + e];
        atomicAdd(&M[d * NN + s], dinv[s] * dinv[d]);
    }
    if (tid < NN) atomicAdd(&M[tid * NN + tid], dinv[tid] * dinv[tid]);
    __syncthreads();

    // h = x @ W_gcn (chunk of 32 cols)
    for (int i = tid; i < NN * 32; i += 256) {
        int s = i >> 5, jj = i & 31;
        float acc = 0.f;
        #pragma unroll
        for (int k = 0; k < IND; k++)
            acc = fmaf(x_s[s * IND + k], wg_s[k * 32 + jj], acc);
        h_s[i] = acc;
    }
    __syncthreads();

    // z = relu(M @ h + b)
    for (int i = tid; i < NN * 32; i += 256) {
        int n = i >> 5, jj = i & 31;
        int col = col0 + jj;
        float acc = bg[col];
        for (int s = 0; s < NN; s++)
            acc = fmaf(M[n * NN + s], h_s[s * 32 + jj], acc);
        g_z[n * H + col] = fmaxf(acc, 0.f);
    }
}

// ---------------------------------------------------------------------------
// K2a: per-node mean / rstd over H
// ---------------------------------------------------------------------------
__global__ void k2_stats() {
    const int n = blockIdx.x, tid = threadIdx.x;
    const float* row = &g_z[n * H];
    float s = 0.f, sq = 0.f;
    for (int j = tid; j < H; j += 256) {
        float v = row[j];
        s += v; sq = fmaf(v, v, sq);
    }
    __shared__ float rs[256], rq[256];
    rs[tid] = s; rq[tid] = sq; __syncthreads();
    for (int o = 128; o > 0; o >>= 1) {
        if (tid < o) { rs[tid] += rs[tid + o]; rq[tid] += rq[tid + o]; }
        __syncthreads();
    }
    if (tid == 0) {
        float mu  = rs[0] * (1.0f / H);
        float var = rq[0] * (1.0f / H) - mu * mu;
        g_stats[n]      = mu;
        g_stats[NN + n] = rsqrtf(var + 1e-5f);
    }
}

// ---------------------------------------------------------------------------
// K2b: fused LayerNorm + global_add_pool -> g_g; also zero accumulators
//      g[j] = ln_g[j] * sum_n rstd_n*(z[n,j]-mu_n) + 81*ln_b[j]
// ---------------------------------------------------------------------------
__global__ void k2b_pool(const float* __restrict__ lng,
                         const float* __restrict__ lnb) {
    __shared__ float mu[NN], rsd[NN];
    const int tid = threadIdx.x;
    if (tid < NN) { mu[tid] = g_stats[tid]; rsd[tid] = g_stats[NN + tid]; }
    __syncthreads();
    const int j = blockIdx.x * 256 + tid;
    float acc = 0.f;
    for (int n = 0; n < NN; n++)
        acc = fmaf(rsd[n], g_z[n * H + j] - mu[n], acc);
    g_g[j] = fmaf(lng[j], acc, (float)NN * lnb[j]);
    g_y[j] = 0.f;
    if (j < ACT) g_logits[j] = 0.f;
}

// ---------------------------------------------------------------------------
// K3: GEMV y = g @ W1  (split-K, float4, atomic combine).  The HBM hog.
// grid (8, 32): blockIdx.x = 1024-col tile, blockIdx.y = 256-row K chunk.
// ---------------------------------------------------------------------------
__global__ void k3_gemv1(const float* __restrict__ W1) {
    __shared__ float gs[256];
    const int tid = threadIdx.x;
    const int c   = blockIdx.x * 1024 + tid * 4;
    const int k0  = blockIdx.y * 256;
    gs[tid] = g_g[k0 + tid];
    __syncthreads();
    float a0 = 0.f, a1 = 0.f, a2 = 0.f, a3 = 0.f;
    const float4* Wp = (const float4*)(W1 + (size_t)k0 * H + c);
    #pragma unroll 8
    for (int j = 0; j < 256; j++) {
        float4 w = Wp[(size_t)j * (H / 4)];
        float gv = gs[j];
        a0 = fmaf(gv, w.x, a0);
        a1 = fmaf(gv, w.y, a1);
        a2 = fmaf(gv, w.z, a2);
        a3 = fmaf(gv, w.w, a3);
    }
    atomicAdd(&g_y[c + 0], a0);
    atomicAdd(&g_y[c + 1], a1);
    atomicAdd(&g_y[c + 2], a2);
    atomicAdd(&g_y[c + 3], a3);
}

// ---------------------------------------------------------------------------
// K4: logits = relu(y + b1) @ W2   (b1+relu folded into the read of y)
// 128 blocks, each owns 64 rows of W2; atomic combine into g_logits.
// ---------------------------------------------------------------------------
__global__ void k4_gemv2(const float* __restrict__ W2,
                         const float* __restrict__ b1) {
    __shared__ float ya[64];
    const int tid = threadIdx.x;
    const int j0  = blockIdx.x * 64;
    if (tid < 64) ya[tid] = fmaxf(g_y[j0 + tid] + b1[j0 + tid], 0.f);
    __syncthreads();
    float a0 = 0.f, a1 = 0.f, a2 = 0.f;
    for (int jj = 0; jj < 64; jj++) {
        const float yv = ya[jj];
        const float* row = W2 + (size_t)(j0 + jj) * ACT;
        a0 = fmaf(yv, row[tid],       a0);
        a1 = fmaf(yv, row[tid + 256], a1);
        if (tid < ACT - 512) a2 = fmaf(yv, row[tid + 512], a2);
    }
    atomicAdd(&g_logits[tid],       a0);
    atomicAdd(&g_logits[tid + 256], a1);
    if (tid < ACT - 512) atomicAdd(&g_logits[tid + 512], a2);
}

// ---------------------------------------------------------------------------
// K5: + b2, log_softmax -> out
// ---------------------------------------------------------------------------
__global__ void k5_softmax(const float* __restrict__ b2,
                           float* __restrict__ out) {
    __shared__ float ls[ACT];
    __shared__ float red[256];
    const int tid = threadIdx.x;
    for (int i = tid; i < ACT; i += 256) ls[i] = g_logits[i] + b2[i];
    __syncthreads();
    float m = -1e30f;
    for (int i = tid; i < ACT; i += 256) m = fmaxf(m, ls[i]);
    red[tid] = m; __syncthreads();
    for (int o = 128; o > 0; o >>= 1) {
        if (tid < o) red[tid] = fmaxf(red[tid], red[tid + o]);
        __syncthreads();
    }
    const float mx = red[0]; __syncthreads();
    float s = 0.f;
    for (int i = tid; i < ACT; i += 256) s += __expf(ls[i] - mx);
    red[tid] = s; __syncthreads();
    for (int o = 128; o > 0; o >>= 1) {
        if (tid < o) red[tid] += red[tid + o];
        __syncthreads();
    }
    const float lse = mx + logf(red[0]);
    for (int i = tid; i < ACT; i += 256) out[i] = ls[i] - lse;
}

// ---------------------------------------------------------------------------
extern "C" void kernel_launch(void* const* d_in, const int* in_sizes, int n_in,
                              void* d_out, int out_size) {
    const float* x   = (const float*)d_in[0];
    const int*   ei  = (const int*)d_in[1];    // int32 (JAX x64 disabled downcasts)
    const float* Wg  = (const float*)d_in[2];
    const float* bg  = (const float*)d_in[3];
    const float* lng = (const float*)d_in[4];
    const float* lnb = (const float*)d_in[5];
    const float* W1  = (const float*)d_in[6];
    const float* b1  = (const float*)d_in[7];
    const float* W2  = (const float*)d_in[8];
    const float* b2  = (const float*)d_in[9];
    float* out = (float*)d_out;

    k1_gcn   <<<H / 32, 256>>>(x, ei, Wg, bg);
    k2_stats <<<NN,     256>>>();
    k2b_pool <<<H / 256,256>>>(lng, lnb);
    k3_gemv1 <<<dim3(8, 32), 256>>>(W1);
    k4_gemv2 <<<H / 64, 256>>>(W2, b1);
    k5_softmax<<<1,     256>>>(b2, out);
}

// round 6
// speedup vs baseline: 1.0803x; 1.0803x over previous
#include <cuda_runtime.h>

#define H     8192
#define NN    81
#define NE    1620
#define IND   10
#define ACT   729

// ---- scratch (static device globals: allowed; zero-initialized at load) ----
__device__ float g_z[NN * H];        // post-relu GCN output [81, 8192]
__device__ float g_sum[NN];          // per-node sum(z)
__device__ float g_sumsq[NN];        // per-node sum(z^2)
__device__ float g_y[H];             // g @ W1 accumulator
__device__ float g_logits[ACT];      // y_act @ W2 accumulator
__device__ unsigned g_ctr;           // last-block counter for K4

// ---------------------------------------------------------------------------
// K1: GCN conv + relu -> g_z, PLUS per-node sum/sumsq (warp-reduced atomics).
// Each block owns 32 hidden columns; builds dense normalized adjacency in smem.
// ---------------------------------------------------------------------------
__global__ void k1_gcn(const float* __restrict__ x,
                       const int* __restrict__ ei,       // int32 [2,1620]
                       const float* __restrict__ Wg,
                       const float* __restrict__ bg) {
    __shared__ float x_s[NN * IND];
    __shared__ float dinv[NN];
    __shared__ float M[NN * NN];
    __shared__ float wg_s[IND * 32];
    __shared__ float h_s[NN * 32];
    const int tid  = threadIdx.x;
    const int col0 = blockIdx.x * 32;

    for (int i = tid; i < NN * IND; i += 256) x_s[i] = x[i];
    if (tid < NN) dinv[tid] = 1.0f;                        // self-loop
    for (int i = tid; i < NN * NN; i += 256) M[i] = 0.f;
    for (int i = tid; i < IND * 32; i += 256)
        wg_s[i] = Wg[(i >> 5) * H + col0 + (i & 31)];
    __syncthreads();

    for (int e = tid; e < NE; e += 256)
        atomicAdd(&dinv[ei[NE + e]], 1.f);                 // in-degree at dst
    __syncthreads();
    if (tid < NN) dinv[tid] = rsqrtf(dinv[tid]);
    __syncthreads();

    for (int e = tid; e < NE; e += 256) {
        int s = ei[e], d = ei[NE + e];
        atomicAdd(&M[d * NN + s], dinv[s] * dinv[d]);
    }
    if (tid < NN) atomicAdd(&M[tid * NN + tid], dinv[tid] * dinv[tid]);
    __syncthreads();

    // h = x @ W_gcn (32-col slice)
    for (int i = tid; i < NN * 32; i += 256) {
        int s = i >> 5, jj = i & 31;
        float acc = 0.f;
        #pragma unroll
        for (int k = 0; k < IND; k++)
            acc = fmaf(x_s[s * IND + k], wg_s[k * 32 + jj], acc);
        h_s[i] = acc;
    }
    __syncthreads();

    // z = relu(M @ h + b); each 32-lane warp-segment handles one node per iter
    for (int i = tid; i < NN * 32; i += 256) {
        int n = i >> 5, jj = i & 31;
        int col = col0 + jj;
        float acc = bg[col];
        for (int s = 0; s < NN; s++)
            acc = fmaf(M[n * NN + s], h_s[s * 32 + jj], acc);
        float v = fmaxf(acc, 0.f);
        g_z[n * H + col] = v;
        // warp reduce sum / sumsq over the 32 cols of node n
        float s1 = v, s2 = v * v;
        #pragma unroll
        for (int off = 16; off > 0; off >>= 1) {
            s1 += __shfl_down_sync(0xffffffffu, s1, off);
            s2 += __shfl_down_sync(0xffffffffu, s2, off);
        }
        if ((tid & 31) == 0) {
            atomicAdd(&g_sum[n],   s1);
            atomicAdd(&g_sumsq[n], s2);
        }
    }
}

// ---------------------------------------------------------------------------
// K3: fused LN+pool prolog + GEMV y = g @ W1 (split-K, pipelined float4).
// grid (8, 64): bx = 1024-col tile, by = 128-row K chunk.
// Each block rebuilds its 128-wide g chunk from L2-resident z (8x redundant,
// cheap) -> no separate stats/pool kernels.
// ---------------------------------------------------------------------------
__global__ void k3_gemv1(const float* __restrict__ W1,
                         const float* __restrict__ lng,
                         const float* __restrict__ lnb) {
    __shared__ float mu_s[NN], rs_s[NN];
    __shared__ float part[256];
    __shared__ float gs[128];
    const int tid = threadIdx.x;
    const int k0  = blockIdx.y * 128;

    if (tid < NN) {
        float s  = g_sum[tid], q = g_sumsq[tid];
        float mu = s * (1.0f / H);
        float var = q * (1.0f / H) - mu * mu;
        mu_s[tid] = mu;
        rs_s[tid] = rsqrtf(var + 1e-5f);
    }
    __syncthreads();

    {   // pooled LN for cols [k0, k0+128): 2 threads per column (node halves)
        int kk = tid >> 1, half = tid & 1;
        int n0 = half ? 41 : 0, n1 = half ? 81 : 41;
        const float* zp = g_z + k0 + kk;
        float acc = 0.f;
        #pragma unroll 8
        for (int n = n0; n < n1; n++)
            acc = fmaf(rs_s[n], zp[n * H] - mu_s[n], acc);
        part[tid] = acc;
    }
    __syncthreads();
    if (tid < 128)
        gs[tid] = fmaf(lng[k0 + tid], part[2 * tid] + part[2 * tid + 1],
                       (float)NN * lnb[k0 + tid]);
    __syncthreads();

    // main stream: 128 rows of W1, software-pipelined 4-deep float4 loads
    const int c = blockIdx.x * 1024 + tid * 4;
    const float4* Wp = (const float4*)(W1 + (size_t)k0 * H + c);
    const size_t str = H / 4;
    float a0 = 0.f, a1 = 0.f, a2 = 0.f, a3 = 0.f;
    float4 buf[4];
    #pragma unroll
    for (int p = 0; p < 4; p++) buf[p] = Wp[(size_t)p * str];
    for (int j = 0; j < 128; j += 4) {
        #pragma unroll
        for (int p = 0; p < 4; p++) {
            float4 w = buf[p];
            int nj = j + 4 + p;
            if (nj < 128) buf[p] = Wp[(size_t)nj * str];
            float gv = gs[j + p];
            a0 = fmaf(gv, w.x, a0);
            a1 = fmaf(gv, w.y, a1);
            a2 = fmaf(gv, w.z, a2);
            a3 = fmaf(gv, w.w, a3);
        }
    }
    atomicAdd(&g_y[c + 0], a0);
    atomicAdd(&g_y[c + 1], a1);
    atomicAdd(&g_y[c + 2], a2);
    atomicAdd(&g_y[c + 3], a3);
}

// ---------------------------------------------------------------------------
// K4: logits = relu(y + b1) @ W2, fused with log_softmax (last-block pattern).
// 256 blocks x 32 rows. Last block also re-zeros accumulators for the next
// graph replay (state identical at entry of every run).
// ---------------------------------------------------------------------------
__global__ void k4_gemv2(const float* __restrict__ W2,
                         const float* __restrict__ b1,
                         const float* __restrict__ b2,
                         float* __restrict__ out) {
    __shared__ float ya[32];
    __shared__ bool  amLast;
    const int tid = threadIdx.x;
    const int j0  = blockIdx.x * 32;
    if (tid < 32) ya[tid] = fmaxf(g_y[j0 + tid] + b1[j0 + tid], 0.f);
    __syncthreads();
    float a0 = 0.f, a1 = 0.f, a2 = 0.f;
    #pragma unroll 4
    for (int jj = 0; jj < 32; jj++) {
        const float yv = ya[jj];
        const float* row = W2 + (size_t)(j0 + jj) * ACT;
        a0 = fmaf(yv, row[tid],       a0);
        a1 = fmaf(yv, row[tid + 256], a1);
        if (tid < ACT - 512) a2 = fmaf(yv, row[tid + 512], a2);
    }
    atomicAdd(&g_logits[tid],       a0);
    atomicAdd(&g_logits[tid + 256], a1);
    if (tid < ACT - 512) atomicAdd(&g_logits[tid + 512], a2);

    __threadfence();
    if (tid == 0) amLast = (atomicAdd(&g_ctr, 1u) == gridDim.x - 1);
    __syncthreads();
    if (!amLast) return;
    __threadfence();

    // ---- log_softmax in the last block ----
    __shared__ float ls[ACT];
    __shared__ float red[256];
    for (int i = tid; i < ACT; i += 256) ls[i] = g_logits[i] + b2[i];
    __syncthreads();
    float m = -1e30f;
    for (int i = tid; i < ACT; i += 256) m = fmaxf(m, ls[i]);
    red[tid] = m; __syncthreads();
    for (int o = 128; o > 0; o >>= 1) {
        if (tid < o) red[tid] = fmaxf(red[tid], red[tid + o]);
        __syncthreads();
    }
    const float mx = red[0]; __syncthreads();
    float s = 0.f;
    for (int i = tid; i < ACT; i += 256) s += __expf(ls[i] - mx);
    red[tid] = s; __syncthreads();
    for (int o = 128; o > 0; o >>= 1) {
        if (tid < o) red[tid] += red[tid + o];
        __syncthreads();
    }
    const float lse = mx + logf(red[0]);
    for (int i = tid; i < ACT; i += 256) out[i] = ls[i] - lse;

    // ---- restore state for the next replay ----
    for (int i = tid; i < H;   i += 256) g_y[i]      = 0.f;
    for (int i = tid; i < ACT; i += 256) g_logits[i] = 0.f;
    if (tid < NN) { g_sum[tid] = 0.f; g_sumsq[tid] = 0.f; }
    if (tid == 0) g_ctr = 0u;
}

// ---------------------------------------------------------------------------
extern "C" void kernel_launch(void* const* d_in, const int* in_sizes, int n_in,
                              void* d_out, int out_size) {
    const float* x   = (const float*)d_in[0];
    const int*   ei  = (const int*)d_in[1];
    const float* Wg  = (const float*)d_in[2];
    const float* bg  = (const float*)d_in[3];
    const float* lng = (const float*)d_in[4];
    const float* lnb = (const float*)d_in[5];
    const float* W1  = (const float*)d_in[6];
    const float* b1  = (const float*)d_in[7];
    const float* W2  = (const float*)d_in[8];
    const float* b2  = (const float*)d_in[9];
    float* out = (float*)d_out;

    k1_gcn   <<<H / 32, 256>>>(x, ei, Wg, bg);
    k3_gemv1 <<<dim3(8, 64), 256>>>(W1, lng, lnb);
    k4_gemv2 <<<256, 256>>>(W2, b1, b2, out);
}